// round 3
// baseline (speedup 1.0000x reference)
#include <cuda_runtime.h>
#include <cstddef>

#define NN   50000
#define FI   128
#define HC   128
#define NH   4
#define EMAX 1600000
#define EAMAX (EMAX + NN)

// ---------------- scratch (device globals; no allocations) ----------------
__device__ alignas(16) float    g_xw1[(size_t)NN * HC];      // 25.6 MB
__device__ alignas(16) float    g_asrc1[NN * NH];
__device__ alignas(16) float    g_adst1[NN * NH];
__device__ alignas(16) unsigned g_amax1[NN * NH];
__device__ alignas(16) float    g_denom1[NN * NH];
__device__ alignas(16) float    g_e1[(size_t)EAMAX * NH];    // 26.4 MB
__device__ alignas(16) float    g_out1[(size_t)NN * HC];     // 25.6 MB
__device__ alignas(16) float    g_xw2[NN];
__device__ alignas(16) unsigned g_amax2[NN];
__device__ alignas(16) float    g_denom2[NN];
__device__ alignas(16) float    g_e2[EAMAX];
__device__ alignas(16) float    g_out2[NN];
__device__ alignas(16) int2     g_edge[EAMAX];               // 13.2 MB packed (src,dst)
__device__ int g_is64;

// ---------------- helpers ----------------
__device__ __forceinline__ unsigned f2o(float f) {
    unsigned u = __float_as_uint(f);
    return u ^ (unsigned)(((int)u >> 31) | 0x80000000);
}
__device__ __forceinline__ float o2f(unsigned u) {
    return (u & 0x80000000u) ? __uint_as_float(u ^ 0x80000000u)
                             : __uint_as_float(~u);
}
__device__ __forceinline__ float lrelu(float v) { return v > 0.f ? v : 0.2f * v; }

__device__ __forceinline__ void red_add_v4(float* p, float a, float b, float c, float d) {
    asm volatile("red.global.add.v4.f32 [%0], {%1,%2,%3,%4};"
                 :: "l"(p), "f"(a), "f"(b), "f"(c), "f"(d) : "memory");
}

__device__ __forceinline__ float warp_sum(float v) {
#pragma unroll
    for (int o = 16; o; o >>= 1) v += __shfl_down_sync(0xffffffffu, v, o);
    return v;
}

// ---------------- edge-index dtype detect + convert ----------------
// If edge_index is int64 (little-endian, values < 2^31), every odd 32-bit word
// of the first 64 entries is 0. For int32 edges that is essentially impossible.
__global__ void k_detect(const int* __restrict__ ei32) {
    if (threadIdx.x == 0 && blockIdx.x == 0) {
        int is64 = 1;
        for (int i = 0; i < 64; i++)
            if (ei32[2 * i + 1] != 0) { is64 = 0; break; }
        g_is64 = is64;
    }
}

__global__ void k_convert(const void* __restrict__ ei, int E, int EA) {
    int e = blockIdx.x * blockDim.x + threadIdx.x;
    if (e >= EA) return;
    int src, dst;
    if (e < E) {
        if (g_is64) {
            src = (int)((const long long*)ei)[e];
            dst = (int)((const long long*)ei)[E + e];
        } else {
            src = ((const int*)ei)[e];
            dst = ((const int*)ei)[E + e];
        }
    } else {
        src = dst = e - E;
    }
    g_edge[e] = make_int2(src, dst);
}

// ---------------- layer 1 GEMM: xw1 = x @ W1^T ----------------
#define GEMM_SMEM ((128 * 129 + 32 * 128) * 4)
__global__ void k_gemm1(const float* __restrict__ x, const float* __restrict__ W1, int N) {
    extern __shared__ float sm[];
    float* Wt = sm;                 // [k*129 + j]
    float* xs = sm + 128 * 129;     // [m*128 + k]
    int tid = threadIdx.x;
    for (int idx = tid; idx < HC * FI; idx += 256) {
        int j = idx >> 7, k = idx & 127;
        Wt[k * 129 + j] = W1[idx];
    }
    int nb = blockIdx.x * 32;
    for (int idx = tid; idx < 32 * FI; idx += 256) {
        int m = idx >> 7;
        int n = nb + m;
        xs[idx] = (n < N) ? x[(size_t)n * FI + (idx & 127)] : 0.f;
    }
    __syncthreads();
    int j = tid & 127, mh = tid >> 7;
    float acc[16];
#pragma unroll
    for (int i = 0; i < 16; i++) acc[i] = 0.f;
    for (int k = 0; k < FI; k++) {
        float w = Wt[k * 129 + j];
#pragma unroll
        for (int i = 0; i < 16; i++) acc[i] += xs[(mh * 16 + i) * FI + k] * w;
    }
#pragma unroll
    for (int i = 0; i < 16; i++) {
        int n = nb + mh * 16 + i;
        if (n < N) g_xw1[(size_t)n * HC + j] = acc[i];
    }
}

// ---------------- per-node attention logits (warp per node) ----------------
__global__ void k_att1(const float* __restrict__ as, const float* __restrict__ ad, int N) {
    int n = (blockIdx.x * blockDim.x + threadIdx.x) >> 5;
    if (n >= N) return;
    int l = threadIdx.x & 31;
    const float* row = &g_xw1[(size_t)n * HC];
#pragma unroll
    for (int h = 0; h < NH; h++) {
        float v = row[h * 32 + l];
        float s = warp_sum(v * as[h * 32 + l]);
        float d = warp_sum(v * ad[h * 32 + l]);
        if (l == 0) { g_asrc1[n * NH + h] = s; g_adst1[n * NH + h] = d; }
    }
}

// ---------------- layer-1 edge pass A: alpha + segment max ----------------
__global__ void k_edgeA1(int EA) {
    int e = blockIdx.x * blockDim.x + threadIdx.x;
    if (e >= EA) return;
    int2 ed = g_edge[e];
    float4 a = *(const float4*)&g_asrc1[ed.x * NH];
    float4 b = *(const float4*)&g_adst1[ed.y * NH];
    float4 al;
    al.x = lrelu(a.x + b.x); al.y = lrelu(a.y + b.y);
    al.z = lrelu(a.z + b.z); al.w = lrelu(a.w + b.w);
    *(float4*)&g_e1[(size_t)e * NH] = al;
    atomicMax(&g_amax1[ed.y * NH + 0], f2o(al.x));
    atomicMax(&g_amax1[ed.y * NH + 1], f2o(al.y));
    atomicMax(&g_amax1[ed.y * NH + 2], f2o(al.z));
    atomicMax(&g_amax1[ed.y * NH + 3], f2o(al.w));
}

__global__ void k_decode(unsigned* p, int n) {
    int i = blockIdx.x * blockDim.x + threadIdx.x;
    if (i < n) p[i] = __float_as_uint(o2f(p[i]));
}

// ---------------- layer-1 edge pass B: exp + segment sum ----------------
__global__ void k_edgeB1(int EA) {
    int e = blockIdx.x * blockDim.x + threadIdx.x;
    if (e >= EA) return;
    int dst = g_edge[e].y;
    float4 al = *(const float4*)&g_e1[(size_t)e * NH];
    float4 am = *reinterpret_cast<const float4*>(&g_amax1[dst * NH]);
    float4 ev;
    ev.x = __expf(al.x - am.x); ev.y = __expf(al.y - am.y);
    ev.z = __expf(al.z - am.z); ev.w = __expf(al.w - am.w);
    *(float4*)&g_e1[(size_t)e * NH] = ev;
    red_add_v4(&g_denom1[dst * NH], ev.x, ev.y, ev.z, ev.w);
}

// ---------------- layer-1 edge pass C: weighted message scatter ----------------
__global__ void k_edgeC1(int EA) {
    int w = (blockIdx.x * blockDim.x + threadIdx.x) >> 5;
    if (w >= EA) return;
    int l = threadIdx.x & 31;
    int2 ed = g_edge[w];
    int h = l >> 3;
    float ev = g_e1[(size_t)w * NH + h];
    float dn = g_denom1[ed.y * NH + h];
    float coef = ev / (dn + 1e-16f);
    float4 v = *(const float4*)&g_xw1[(size_t)ed.x * HC + 4 * l];
    red_add_v4(&g_out1[(size_t)ed.y * HC + 4 * l],
               v.x * coef, v.y * coef, v.z * coef, v.w * coef);
}

// ---------------- fused bias+ReLU+GEMV ----------------
__global__ void k_gemv2(const float* __restrict__ b1, const float* __restrict__ W2, int N) {
    int n = (blockIdx.x * blockDim.x + threadIdx.x) >> 5;
    if (n >= N) return;
    int l = threadIdx.x & 31;
    float acc = 0.f;
#pragma unroll
    for (int i = 0; i < 4; i++) {
        int c = i * 32 + l;
        float hv = g_out1[(size_t)n * HC + c] + b1[c];
        hv = hv > 0.f ? hv : 0.f;
        acc += hv * W2[c];
    }
    acc = warp_sum(acc);
    if (l == 0) g_xw2[n] = acc;
}

// ---------------- layer-2 edge passes (scalar head) ----------------
__global__ void k_edgeA2(const float* __restrict__ as2, const float* __restrict__ ad2, int EA) {
    int e = blockIdx.x * blockDim.x + threadIdx.x;
    if (e >= EA) return;
    int2 ed = g_edge[e];
    float a = lrelu(g_xw2[ed.x] * as2[0] + g_xw2[ed.y] * ad2[0]);
    g_e2[e] = a;
    atomicMax(&g_amax2[ed.y], f2o(a));
}

__global__ void k_edgeB2(int EA) {
    int e = blockIdx.x * blockDim.x + threadIdx.x;
    if (e >= EA) return;
    int dst = g_edge[e].y;
    float ev = __expf(g_e2[e] - __uint_as_float(g_amax2[dst]));
    g_e2[e] = ev;
    atomicAdd(&g_denom2[dst], ev);
}

__global__ void k_edgeC2(int EA) {
    int e = blockIdx.x * blockDim.x + threadIdx.x;
    if (e >= EA) return;
    int2 ed = g_edge[e];
    float coef = g_e2[e] / (g_denom2[ed.y] + 1e-16f);
    atomicAdd(&g_out2[ed.y], g_xw2[ed.x] * coef);
}

__global__ void k_final(const float* __restrict__ b2, float* __restrict__ out, int N) {
    int n = blockIdx.x * blockDim.x + threadIdx.x;
    if (n < N) out[n] = g_out2[n] + b2[0];
}

// ---------------- launch ----------------
extern "C" void kernel_launch(void* const* d_in, const int* in_sizes, int n_in,
                              void* d_out, int out_size) {
    const float* x   = (const float*)d_in[0];
    const void*  ei  = d_in[1];
    const float* W1  = (const float*)d_in[2];
    const float* as1 = (const float*)d_in[3];
    const float* ad1 = (const float*)d_in[4];
    const float* b1  = (const float*)d_in[5];
    const float* W2  = (const float*)d_in[6];
    const float* as2 = (const float*)d_in[7];
    const float* ad2 = (const float*)d_in[8];
    const float* b2  = (const float*)d_in[9];

    int N  = in_sizes[0] / FI;
    int E  = in_sizes[1] / 2;
    int EA = E + N;

    void *pamax1, *pden1, *pout1, *pamax2, *pden2, *pout2;
    cudaGetSymbolAddress(&pamax1, g_amax1);
    cudaGetSymbolAddress(&pden1,  g_denom1);
    cudaGetSymbolAddress(&pout1,  g_out1);
    cudaGetSymbolAddress(&pamax2, g_amax2);
    cudaGetSymbolAddress(&pden2,  g_denom2);
    cudaGetSymbolAddress(&pout2,  g_out2);

    cudaMemsetAsync(pamax1, 0, (size_t)N * NH * sizeof(unsigned), 0);
    cudaMemsetAsync(pden1,  0, (size_t)N * NH * sizeof(float), 0);
    cudaMemsetAsync(pout1,  0, (size_t)N * HC * sizeof(float), 0);
    cudaMemsetAsync(pamax2, 0, (size_t)N * sizeof(unsigned), 0);
    cudaMemsetAsync(pden2,  0, (size_t)N * sizeof(float), 0);
    cudaMemsetAsync(pout2,  0, (size_t)N * sizeof(float), 0);

    cudaFuncSetAttribute(k_gemm1, cudaFuncAttributeMaxDynamicSharedMemorySize, GEMM_SMEM);

    int eb = (EA + 255) / 256;
    k_detect<<<1, 32>>>((const int*)ei);
    k_convert<<<eb, 256>>>(ei, E, EA);

    k_gemm1<<<(N + 31) / 32, 256, GEMM_SMEM>>>(x, W1, N);
    k_att1<<<((size_t)N * 32 + 127) / 128, 128>>>(as1, ad1, N);

    k_edgeA1<<<eb, 256>>>(EA);
    k_decode<<<(N * NH + 255) / 256, 256>>>((unsigned*)pamax1, N * NH);
    k_edgeB1<<<eb, 256>>>(EA);
    k_edgeC1<<<((size_t)EA * 32 + 255) / 256, 256>>>(EA);

    k_gemv2<<<((size_t)N * 32 + 255) / 256, 256>>>(b1, W2, N);

    k_edgeA2<<<eb, 256>>>(as2, ad2, EA);
    k_decode<<<(N + 255) / 256, 256>>>((unsigned*)pamax2, N);
    k_edgeB2<<<eb, 256>>>(EA);
    k_edgeC2<<<eb, 256>>>(EA);

    k_final<<<(N + 255) / 256, 256>>>(b2, (float*)d_out, N);
}

// round 4
// speedup vs baseline: 1.6861x; 1.6861x over previous
#include <cuda_runtime.h>
#include <cstddef>

#define NN   50000
#define FI   128
#define HC   128
#define NH   4
#define EMAX 1600000
#define EAMAX (EMAX + NN)

// ---------------- scratch (device globals; no allocations) ----------------
__device__ alignas(16) float g_xw1[(size_t)NN * HC];   // 25.6 MB
__device__ alignas(16) float g_asrc1[NN * NH];
__device__ alignas(16) float g_adst1[NN * NH];
__device__ alignas(16) float g_xw2[NN];
__device__ int g_deg[NN];
__device__ int g_off[NN + 1];
__device__ int g_cur[NN];
__device__ int g_csr[EAMAX];                           // src per edge, grouped by dst
__device__ int g_is64;

// ---------------- helpers ----------------
__device__ __forceinline__ float lrelu(float v) { return v > 0.f ? v : 0.2f * v; }

__device__ __forceinline__ float warp_sum(float v) {
#pragma unroll
    for (int o = 16; o; o >>= 1) v += __shfl_down_sync(0xffffffffu, v, o);
    return v;
}

// ---------------- edge-index dtype detect ----------------
// int64 node ids < 2^31 -> every odd 32-bit word of first 64 entries is 0.
__global__ void k_detect(const int* __restrict__ ei32) {
    if (threadIdx.x == 0) {
        int is64 = 1;
        for (int i = 0; i < 64; i++)
            if (ei32[2 * i + 1] != 0) { is64 = 0; break; }
        g_is64 = is64;
    }
}

__device__ __forceinline__ int load_idx(const void* ei, int pos) {
    return g_is64 ? (int)((const long long*)ei)[pos] : ((const int*)ei)[pos];
}

// ---------------- CSR build: count / scan / fill ----------------
__global__ void k_count(const void* __restrict__ ei, int E, int EA) {
    int e = blockIdx.x * blockDim.x + threadIdx.x;
    if (e >= EA) return;
    int dst = (e < E) ? load_idx(ei, E + e) : (e - E);
    atomicAdd(&g_deg[dst], 1);
}

// single block, 1024 threads: exclusive scan of g_deg -> g_off, g_cur
__global__ void k_scan(int N, int EA) {
    __shared__ int part[1024];
    int t = threadIdx.x;
    int chunk = (N + 1023) / 1024;
    int s0 = t * chunk, s1 = min(s0 + chunk, N);
    int s = 0;
    for (int i = s0; i < s1; i++) s += g_deg[i];
    part[t] = s;
    __syncthreads();
    for (int o = 1; o < 1024; o <<= 1) {
        int v = (t >= o) ? part[t - o] : 0;
        __syncthreads();
        part[t] += v;
        __syncthreads();
    }
    int run = t ? part[t - 1] : 0;
    for (int i = s0; i < s1; i++) {
        g_off[i] = run;
        g_cur[i] = run;
        run += g_deg[i];
    }
    if (t == 1023) g_off[N] = EA;
}

__global__ void k_fill(const void* __restrict__ ei, int E, int EA) {
    int e = blockIdx.x * blockDim.x + threadIdx.x;
    if (e >= EA) return;
    int src, dst;
    if (e < E) { src = load_idx(ei, e); dst = load_idx(ei, E + e); }
    else       { src = dst = e - E; }
    int p = atomicAdd(&g_cur[dst], 1);
    g_csr[p] = src;
}

// ---------------- layer 1 GEMM: xw1 = x @ W1^T ----------------
#define GEMM_SMEM ((128 * 129 + 32 * 128) * 4)
__global__ void k_gemm1(const float* __restrict__ x, const float* __restrict__ W1, int N) {
    extern __shared__ float sm[];
    float* Wt = sm;                 // [k*129 + j]
    float* xs = sm + 128 * 129;     // [m*128 + k]
    int tid = threadIdx.x;
    for (int idx = tid; idx < HC * FI; idx += 256) {
        int j = idx >> 7, k = idx & 127;
        Wt[k * 129 + j] = W1[idx];
    }
    int nb = blockIdx.x * 32;
    for (int idx = tid; idx < 32 * FI; idx += 256) {
        int m = idx >> 7;
        int n = nb + m;
        xs[idx] = (n < N) ? x[(size_t)n * FI + (idx & 127)] : 0.f;
    }
    __syncthreads();
    int j = tid & 127, mh = tid >> 7;
    float acc[16];
#pragma unroll
    for (int i = 0; i < 16; i++) acc[i] = 0.f;
    for (int k = 0; k < FI; k++) {
        float w = Wt[k * 129 + j];
#pragma unroll
        for (int i = 0; i < 16; i++) acc[i] += xs[(mh * 16 + i) * FI + k] * w;
    }
#pragma unroll
    for (int i = 0; i < 16; i++) {
        int n = nb + mh * 16 + i;
        if (n < N) g_xw1[(size_t)n * HC + j] = acc[i];
    }
}

// ---------------- per-node attention logits (warp per node) ----------------
__global__ void k_att1(const float* __restrict__ as, const float* __restrict__ ad, int N) {
    int n = (blockIdx.x * blockDim.x + threadIdx.x) >> 5;
    if (n >= N) return;
    int l = threadIdx.x & 31;
    const float* row = &g_xw1[(size_t)n * HC];
#pragma unroll
    for (int h = 0; h < NH; h++) {
        float v = row[h * 32 + l];
        float s = warp_sum(v * as[h * 32 + l]);
        float d = warp_sum(v * ad[h * 32 + l]);
        if (l == 0) { g_asrc1[n * NH + h] = s; g_adst1[n * NH + h] = d; }
    }
}

// ---------------- layer-1 fused: softmax-gather + bias + ReLU + GEMV ----------------
// warp per dst node; lane l covers cols 4l..4l+3 (head h=l>>3).
// No max-subtraction (softmax is shift-invariant; |alpha| <~ 4 here).
__global__ void k_l1(const float* __restrict__ b1, const float* __restrict__ W2, int N) {
    int n = (blockIdx.x * blockDim.x + threadIdx.x) >> 5;
    if (n >= N) return;
    int l = threadIdx.x & 31;
    int h = l >> 3;
    int beg = g_off[n], end = g_off[n + 1];
    float adh = g_adst1[n * NH + h];
    float ax = 0.f, ay = 0.f, az = 0.f, aw = 0.f, den = 0.f;
    for (int e = beg; e < end; e++) {
        int src = g_csr[e];
        float a = g_asrc1[src * NH + h] + adh;
        float ex = __expf(lrelu(a));
        den += ex;
        float4 v = *(const float4*)&g_xw1[(size_t)src * HC + 4 * l];
        ax += ex * v.x; ay += ex * v.y; az += ex * v.z; aw += ex * v.w;
    }
    float inv = 1.f / (den + 1e-16f);
    float4 bb = *(const float4*)&b1[4 * l];
    float4 ww = *(const float4*)&W2[4 * l];
    float s = fmaxf(ax * inv + bb.x, 0.f) * ww.x
            + fmaxf(ay * inv + bb.y, 0.f) * ww.y
            + fmaxf(az * inv + bb.z, 0.f) * ww.z
            + fmaxf(aw * inv + bb.w, 0.f) * ww.w;
    s = warp_sum(s);
    if (l == 0) g_xw2[n] = s;
}

// ---------------- layer-2 fused: softmax-gather + bias -> d_out ----------------
__global__ void k_l2(const float* __restrict__ as2, const float* __restrict__ ad2,
                     const float* __restrict__ b2, float* __restrict__ out, int N) {
    int n = (blockIdx.x * blockDim.x + threadIdx.x) >> 5;
    if (n >= N) return;
    int l = threadIdx.x & 31;
    int beg = g_off[n], end = g_off[n + 1];
    float xd = g_xw2[n] * ad2[0];
    float asc = as2[0];
    float den = 0.f, num = 0.f;
    for (int e = beg + l; e < end; e += 32) {
        float xs = g_xw2[g_csr[e]];
        float ex = __expf(lrelu(xs * asc + xd));
        den += ex;
        num += ex * xs;
    }
    den = warp_sum(den);
    num = warp_sum(num);
    if (l == 0) out[n] = num / (den + 1e-16f) + b2[0];
}

// ---------------- launch ----------------
extern "C" void kernel_launch(void* const* d_in, const int* in_sizes, int n_in,
                              void* d_out, int out_size) {
    const float* x   = (const float*)d_in[0];
    const void*  ei  = d_in[1];
    const float* W1  = (const float*)d_in[2];
    const float* as1 = (const float*)d_in[3];
    const float* ad1 = (const float*)d_in[4];
    const float* b1  = (const float*)d_in[5];
    const float* W2  = (const float*)d_in[6];
    const float* as2 = (const float*)d_in[7];
    const float* ad2 = (const float*)d_in[8];
    const float* b2  = (const float*)d_in[9];

    int N  = in_sizes[0] / FI;
    int E  = in_sizes[1] / 2;
    int EA = E + N;

    void* pdeg;
    cudaGetSymbolAddress(&pdeg, g_deg);
    cudaMemsetAsync(pdeg, 0, (size_t)N * sizeof(int), 0);

    cudaFuncSetAttribute(k_gemm1, cudaFuncAttributeMaxDynamicSharedMemorySize, GEMM_SMEM);

    int eb = (EA + 255) / 256;
    k_detect<<<1, 32>>>((const int*)ei);
    k_count<<<eb, 256>>>(ei, E, EA);
    k_scan<<<1, 1024>>>(N, EA);
    k_fill<<<eb, 256>>>(ei, E, EA);

    k_gemm1<<<(N + 31) / 32, 256, GEMM_SMEM>>>(x, W1, N);
    k_att1<<<((size_t)N * 32 + 127) / 128, 128>>>(as1, ad1, N);

    k_l1<<<((size_t)N * 32 + 255) / 256, 256>>>(b1, W2, N);
    k_l2<<<((size_t)N * 32 + 255) / 256, 256>>>(as2, ad2, b2, (float*)d_out, N);
}

// round 5
// speedup vs baseline: 1.7557x; 1.0413x over previous
#include <cuda_runtime.h>
#include <cstddef>

#define NN   50000
#define FI   128
#define HC   128
#define NH   4
#define EMAX 1600000
#define EAMAX (EMAX + NN)

// ---------------- scratch (device globals; no allocations) ----------------
__device__ alignas(16) float g_xw1[(size_t)NN * HC];   // 25.6 MB
__device__ alignas(16) float g_asrc1[NN * NH];
__device__ alignas(16) float g_adst1[NN * NH];
__device__ alignas(16) float g_xw2[NN];
__device__ int g_deg[NN];
__device__ int g_off[NN + 1];
__device__ int g_cur[NN];
__device__ int g_csr[EAMAX];                           // src per edge, grouped by dst
__device__ int g_is64;

// ---------------- helpers ----------------
__device__ __forceinline__ float lrelu(float v) { return v > 0.f ? v : 0.2f * v; }

__device__ __forceinline__ float warp_sum(float v) {
#pragma unroll
    for (int o = 16; o; o >>= 1) v += __shfl_down_sync(0xffffffffu, v, o);
    return v;
}

// ---------------- edge-index dtype detect ----------------
__global__ void k_detect(const int* __restrict__ ei32) {
    if (threadIdx.x == 0) {
        int is64 = 1;
        for (int i = 0; i < 64; i++)
            if (ei32[2 * i + 1] != 0) { is64 = 0; break; }
        g_is64 = is64;
    }
}

__device__ __forceinline__ int load_idx(const void* ei, int pos) {
    return g_is64 ? (int)((const long long*)ei)[pos] : ((const int*)ei)[pos];
}

// ---------------- CSR build: count / scan / fill ----------------
__global__ void k_count(const void* __restrict__ ei, int E, int EA) {
    int e = blockIdx.x * blockDim.x + threadIdx.x;
    if (e >= EA) return;
    int dst = (e < E) ? load_idx(ei, E + e) : (e - E);
    atomicAdd(&g_deg[dst], 1);
}

__global__ void k_scan(int N, int EA) {
    __shared__ int part[1024];
    int t = threadIdx.x;
    int chunk = (N + 1023) / 1024;
    int s0 = t * chunk, s1 = min(s0 + chunk, N);
    int s = 0;
    for (int i = s0; i < s1; i++) s += g_deg[i];
    part[t] = s;
    __syncthreads();
    for (int o = 1; o < 1024; o <<= 1) {
        int v = (t >= o) ? part[t - o] : 0;
        __syncthreads();
        part[t] += v;
        __syncthreads();
    }
    int run = t ? part[t - 1] : 0;
    for (int i = s0; i < s1; i++) {
        g_off[i] = run;
        g_cur[i] = run;
        run += g_deg[i];
    }
    if (t == 1023) g_off[N] = EA;
}

__global__ void k_fill(const void* __restrict__ ei, int E, int EA) {
    int e = blockIdx.x * blockDim.x + threadIdx.x;
    if (e >= EA) return;
    int src, dst;
    if (e < E) { src = load_idx(ei, e); dst = load_idx(ei, E + e); }
    else       { src = dst = e - E; }
    int p = atomicAdd(&g_cur[dst], 1);
    g_csr[p] = src;
}

// ---------------- layer 1 GEMM + fused attention logits ----------------
// block = 256 threads, 32 nodes/block. Wt in smem transposed (pad 129).
// Warp w handles cols j = (w&3)*32..+31 == head h=(w&3), rows mh=w>>2.
#define GEMM_SMEM ((128 * 129 + 32 * 128) * 4)
__global__ void k_gemm1(const float* __restrict__ x, const float* __restrict__ W1,
                        const float* __restrict__ as1, const float* __restrict__ ad1,
                        int N) {
    extern __shared__ float sm[];
    float* Wt = sm;                 // [k*129 + j]
    float* xs = sm + 128 * 129;     // [m*128 + k]
    int tid = threadIdx.x;
    for (int idx = tid; idx < HC * FI; idx += 256) {
        int j = idx >> 7, k = idx & 127;
        Wt[k * 129 + j] = W1[idx];
    }
    int nb = blockIdx.x * 32;
    for (int idx = tid; idx < 32 * FI; idx += 256) {
        int m = idx >> 7;
        int n = nb + m;
        xs[idx] = (n < N) ? x[(size_t)n * FI + (idx & 127)] : 0.f;
    }
    __syncthreads();
    int j = tid & 127, mh = tid >> 7;
    float acc[16];
#pragma unroll
    for (int i = 0; i < 16; i++) acc[i] = 0.f;
    for (int k = 0; k < FI; k += 4) {
        float w0 = Wt[(k + 0) * 129 + j];
        float w1 = Wt[(k + 1) * 129 + j];
        float w2 = Wt[(k + 2) * 129 + j];
        float w3 = Wt[(k + 3) * 129 + j];
#pragma unroll
        for (int i = 0; i < 16; i++) {
            float4 xv = *(const float4*)&xs[(mh * 16 + i) * FI + k];
            acc[i] += xv.x * w0 + xv.y * w1 + xv.z * w2 + xv.w * w3;
        }
    }
    // store xw1
#pragma unroll
    for (int i = 0; i < 16; i++) {
        int n = nb + mh * 16 + i;
        if (n < N) g_xw1[(size_t)n * HC + j] = acc[i];
    }
    // fused attention logits: this warp covers exactly head h over 32 cols
    int l = tid & 31;
    int h = (tid >> 5) & 3;
    float av = as1[j];   // att_src1 flattened [H*C] == [j]
    float dv = ad1[j];
#pragma unroll
    for (int i = 0; i < 16; i++) {
        float s = warp_sum(acc[i] * av);
        float d = warp_sum(acc[i] * dv);
        int n = nb + mh * 16 + i;
        if (l == 0 && n < N) {
            g_asrc1[n * NH + h] = s;
            g_adst1[n * NH + h] = d;
        }
    }
}

// ---------------- layer-1 fused: softmax-gather + bias + ReLU + GEMV ----------------
__global__ void k_l1(const float* __restrict__ b1, const float* __restrict__ W2, int N) {
    int n = (blockIdx.x * blockDim.x + threadIdx.x) >> 5;
    if (n >= N) return;
    int l = threadIdx.x & 31;
    int h = l >> 3;
    int beg = g_off[n], end = g_off[n + 1];
    float adh = g_adst1[n * NH + h];
    float ax = 0.f, ay = 0.f, az = 0.f, aw = 0.f, den = 0.f;
    for (int e = beg; e < end; e++) {
        int src = g_csr[e];
        float a = g_asrc1[src * NH + h] + adh;
        float ex = __expf(lrelu(a));
        den += ex;
        float4 v = *(const float4*)&g_xw1[(size_t)src * HC + 4 * l];
        ax += ex * v.x; ay += ex * v.y; az += ex * v.z; aw += ex * v.w;
    }
    float inv = 1.f / (den + 1e-16f);
    float4 bb = *(const float4*)&b1[4 * l];
    float4 ww = *(const float4*)&W2[4 * l];
    float s = fmaxf(ax * inv + bb.x, 0.f) * ww.x
            + fmaxf(ay * inv + bb.y, 0.f) * ww.y
            + fmaxf(az * inv + bb.z, 0.f) * ww.z
            + fmaxf(aw * inv + bb.w, 0.f) * ww.w;
    s = warp_sum(s);
    if (l == 0) g_xw2[n] = s;
}

// ---------------- layer-2 fused: softmax-gather + bias -> d_out ----------------
__global__ void k_l2(const float* __restrict__ as2, const float* __restrict__ ad2,
                     const float* __restrict__ b2, float* __restrict__ out, int N) {
    int n = (blockIdx.x * blockDim.x + threadIdx.x) >> 5;
    if (n >= N) return;
    int l = threadIdx.x & 31;
    int beg = g_off[n], end = g_off[n + 1];
    float xd = g_xw2[n] * ad2[0];
    float asc = as2[0];
    float den = 0.f, num = 0.f;
    for (int e = beg + l; e < end; e += 32) {
        float xs = g_xw2[g_csr[e]];
        float ex = __expf(lrelu(xs * asc + xd));
        den += ex;
        num += ex * xs;
    }
    den = warp_sum(den);
    num = warp_sum(num);
    if (l == 0) out[n] = num / (den + 1e-16f) + b2[0];
}

// ---------------- launch ----------------
extern "C" void kernel_launch(void* const* d_in, const int* in_sizes, int n_in,
                              void* d_out, int out_size) {
    const float* x   = (const float*)d_in[0];
    const void*  ei  = d_in[1];
    const float* W1  = (const float*)d_in[2];
    const float* as1 = (const float*)d_in[3];
    const float* ad1 = (const float*)d_in[4];
    const float* b1  = (const float*)d_in[5];
    const float* W2  = (const float*)d_in[6];
    const float* as2 = (const float*)d_in[7];
    const float* ad2 = (const float*)d_in[8];
    const float* b2  = (const float*)d_in[9];

    int N  = in_sizes[0] / FI;
    int E  = in_sizes[1] / 2;
    int EA = E + N;

    // one-time side stream + events (host resources, not device memory)
    static cudaStream_t s_csr = nullptr;
    static cudaEvent_t ev_fork = nullptr, ev_join = nullptr;
    if (!s_csr) {
        cudaStreamCreateWithFlags(&s_csr, cudaStreamNonBlocking);
        cudaEventCreateWithFlags(&ev_fork, cudaEventDisableTiming);
        cudaEventCreateWithFlags(&ev_join, cudaEventDisableTiming);
    }

    void* pdeg;
    cudaGetSymbolAddress(&pdeg, g_deg);
    cudaMemsetAsync(pdeg, 0, (size_t)N * sizeof(int), 0);

    cudaFuncSetAttribute(k_gemm1, cudaFuncAttributeMaxDynamicSharedMemorySize, GEMM_SMEM);

    // fork: CSR build on side stream
    cudaEventRecord(ev_fork, 0);
    cudaStreamWaitEvent(s_csr, ev_fork, 0);
    int eb = (EA + 255) / 256;
    k_detect<<<1, 32, 0, s_csr>>>((const int*)ei);
    k_count<<<eb, 256, 0, s_csr>>>(ei, E, EA);
    k_scan<<<1, 1024, 0, s_csr>>>(N, EA);
    k_fill<<<eb, 256, 0, s_csr>>>(ei, E, EA);
    cudaEventRecord(ev_join, s_csr);

    // main stream: GEMM (+ fused attention logits)
    k_gemm1<<<(N + 31) / 32, 256, GEMM_SMEM>>>(x, W1, as1, ad1, N);

    // join, then fused layers
    cudaStreamWaitEvent(0, ev_join, 0);
    k_l1<<<((size_t)N * 32 + 255) / 256, 256>>>(b1, W2, N);
    k_l2<<<((size_t)N * 32 + 255) / 256, 256>>>(as2, ad2, b2, (float*)d_out, N);
}